// round 11
// baseline (speedup 1.0000x reference)
#include <cuda_runtime.h>
#include <cuda_bf16.h>

#define D 1024
#define THREADS 256
#define WARPS_PER_CTA (THREADS / 32)
#define VEC 8               // float4 chunks per lane per row: D / 4 / 32 = 8
#define EPS 5e-05f

__device__ __forceinline__ void load_row(float4 (&v)[VEC],
                                         const float* __restrict__ x,
                                         int row, int lane)
{
    const float4* __restrict__ xr =
        reinterpret_cast<const float4*>(x + (long long)row * D);
    #pragma unroll
    for (int i = 0; i < VEC; i++) v[i] = xr[lane + 32 * i];
}

__device__ __forceinline__ void process_row(const float4 (&v)[VEC],
                                            float* __restrict__ out,
                                            const float4* __restrict__ shw,
                                            const float4* __restrict__ shb,
                                            int row, int lane)
{
    float s = 0.0f, sq = 0.0f;
    #pragma unroll
    for (int i = 0; i < VEC; i++) {
        s  += v[i].x + v[i].y + v[i].z + v[i].w;
        sq += v[i].x * v[i].x + v[i].y * v[i].y
            + v[i].z * v[i].z + v[i].w * v[i].w;
    }

    #pragma unroll
    for (int off = 16; off > 0; off >>= 1) {
        s  += __shfl_xor_sync(0xFFFFFFFFu, s,  off);
        sq += __shfl_xor_sync(0xFFFFFFFFu, sq, off);
    }

    const float inv_d = 1.0f / (float)D;
    const float mean = s * inv_d;
    const float var  = sq * inv_d - mean * mean;

    // Reference's 4-step loop: _loop(inp,a) = (inp/a + a)*0.5.
    // a/a == 1.0 exactly; remaining divides by a -> multiply by rcp(a).
    const float a  = var + EPS;
    const float r  = __frcp_rn(a);
    const float l1 = (1.0f   + a) * 0.5f;
    const float l2 = (l1 * r + a) * 0.5f;
    const float l3 = (l2 * r + a) * 0.5f;
    const float sd = (l3 * r + a) * 0.5f;
    const float rstd = __frcp_rn(sd);

    float4* __restrict__ orow =
        reinterpret_cast<float4*>(out + (long long)row * D);
    #pragma unroll
    for (int i = 0; i < VEC; i++) {
        const float4 wv = shw[lane + 32 * i];
        const float4 bv = shb[lane + 32 * i];
        float4 o;
        o.x = (v[i].x - mean) * rstd * wv.x + bv.x;
        o.y = (v[i].y - mean) * rstd * wv.y + bv.y;
        o.z = (v[i].z - mean) * rstd * wv.z + bv.z;
        o.w = (v[i].w - mean) * rstd * wv.w + bv.w;
        orow[lane + 32 * i] = o;
    }
}

__global__ __launch_bounds__(THREADS, 2)
void qlayernorm_pipe_kernel(const float* __restrict__ x,
                            const float* __restrict__ w,
                            const float* __restrict__ b,
                            float* __restrict__ out,
                            int rows)
{
    __shared__ float4 shw[D / 4];
    __shared__ float4 shb[D / 4];

    const int t     = threadIdx.x;
    const int lane  = t & 31;
    const int warp  = t >> 5;
    const int gwarp = blockIdx.x * WARPS_PER_CTA + warp;
    const int stride = gridDim.x * WARPS_PER_CTA;

    shw[t] = reinterpret_cast<const float4*>(w)[t];
    shb[t] = reinterpret_cast<const float4*>(b)[t];
    __syncthreads();

    // Software pipeline: issue next row's loads before reducing/storing the
    // current row, so DRAM requests stay outstanding during the compute phase.
    int r = gwarp;
    if (r >= rows) return;

    float4 va[VEC], vb[VEC];
    load_row(va, x, r, lane);

    while (true) {
        // --- stage A: prefetch into vb, process va ---
        int rn = r + stride;
        if (rn < rows) load_row(vb, x, rn, lane);
        process_row(va, out, shw, shb, r, lane);
        if (rn >= rows) break;
        r = rn;

        // --- stage B: prefetch into va, process vb ---
        rn = r + stride;
        if (rn < rows) load_row(va, x, rn, lane);
        process_row(vb, out, shw, shb, r, lane);
        if (rn >= rows) break;
        r = rn;
    }
}

extern "C" void kernel_launch(void* const* d_in, const int* in_sizes, int n_in,
                              void* d_out, int out_size)
{
    const float* x = (const float*)d_in[0];
    const float* w = (const float*)d_in[1];
    const float* b = (const float*)d_in[2];
    float* out = (float*)d_out;

    const int rows = in_sizes[0] / D;   // 32768 for B=4, S=8192

    // Persistent: 2 CTAs per SM (148 SMs); each warp pipelines rows.
    const int grid = 2 * 148;
    qlayernorm_pipe_kernel<<<grid, THREADS>>>(x, w, b, out, rows);
}

// round 14
// speedup vs baseline: 1.0046x; 1.0046x over previous
#include <cuda_runtime.h>
#include <cuda_bf16.h>

#define D 1024
#define THREADS 256
#define WARPS_PER_CTA (THREADS / 32)
#define VEC 8               // float4 chunks per lane per row: D / 4 / 32 = 8
#define EPS 5e-05f

// 3 CTAs/SM: 24 warps/SM, register cap ~80 — enough to front-batch all 8
// LDG.128 AND hold v[8] live (the R6 regression came from the 64-reg squeeze
// destroying load batching, not from occupancy itself).
__global__ __launch_bounds__(THREADS, 3)
void qlayernorm_warp3_kernel(const float* __restrict__ x,
                             const float* __restrict__ w,
                             const float* __restrict__ b,
                             float* __restrict__ out,
                             int rows)
{
    __shared__ float4 shw[D / 4];
    __shared__ float4 shb[D / 4];

    const int t     = threadIdx.x;
    const int lane  = t & 31;
    const int warp  = t >> 5;
    const int gwarp = blockIdx.x * WARPS_PER_CTA + warp;
    const int total_warps = gridDim.x * WARPS_PER_CTA;

    // Stage weight/bias into shared once per (persistent) CTA.
    shw[t] = reinterpret_cast<const float4*>(w)[t];
    shb[t] = reinterpret_cast<const float4*>(b)[t];
    __syncthreads();

    const float inv_d = 1.0f / (float)D;

    for (int row = gwarp; row < rows; row += total_warps) {
        const float4* __restrict__ xr =
            reinterpret_cast<const float4*>(x + (long long)row * D);
        float4* __restrict__ orow =
            reinterpret_cast<float4*>(out + (long long)row * D);

        // 8 independent LDG.128 per lane — front-batched, row in registers.
        float4 v[VEC];
        #pragma unroll
        for (int i = 0; i < VEC; i++) v[i] = xr[lane + 32 * i];

        float s = 0.0f, sq = 0.0f;
        #pragma unroll
        for (int i = 0; i < VEC; i++) {
            s  += v[i].x + v[i].y + v[i].z + v[i].w;
            sq += v[i].x * v[i].x + v[i].y * v[i].y
                + v[i].z * v[i].z + v[i].w * v[i].w;
        }

        // Warp-only reduction: no shared memory, no barrier.
        #pragma unroll
        for (int off = 16; off > 0; off >>= 1) {
            s  += __shfl_xor_sync(0xFFFFFFFFu, s,  off);
            sq += __shfl_xor_sync(0xFFFFFFFFu, sq, off);
        }

        const float mean = s * inv_d;
        const float var  = sq * inv_d - mean * mean;

        // Reference's 4-step loop: _loop(inp,a) = (inp/a + a)*0.5.
        // a/a == 1.0 exactly; remaining divides by a -> multiply by rcp(a).
        const float a  = var + EPS;
        const float r  = __frcp_rn(a);
        const float l1 = (1.0f   + a) * 0.5f;
        const float l2 = (l1 * r + a) * 0.5f;
        const float l3 = (l2 * r + a) * 0.5f;
        const float sd = (l3 * r + a) * 0.5f;
        const float rstd = __frcp_rn(sd);

        #pragma unroll
        for (int i = 0; i < VEC; i++) {
            const float4 wv = shw[lane + 32 * i];
            const float4 bv = shb[lane + 32 * i];
            float4 o;
            o.x = (v[i].x - mean) * rstd * wv.x + bv.x;
            o.y = (v[i].y - mean) * rstd * wv.y + bv.y;
            o.z = (v[i].z - mean) * rstd * wv.z + bv.z;
            o.w = (v[i].w - mean) * rstd * wv.w + bv.w;
            orow[lane + 32 * i] = o;
        }
    }
}

extern "C" void kernel_launch(void* const* d_in, const int* in_sizes, int n_in,
                              void* d_out, int out_size)
{
    const float* x = (const float*)d_in[0];
    const float* w = (const float*)d_in[1];
    const float* b = (const float*)d_in[2];
    float* out = (float*)d_out;

    const int rows = in_sizes[0] / D;   // 32768 for B=4, S=8192

    // Persistent: 3 CTAs per SM (148 SMs), warp-per-row.
    const int grid = 3 * 148;
    qlayernorm_warp3_kernel<<<grid, THREADS>>>(x, w, b, out, rows);
}